// round 6
// baseline (speedup 1.0000x reference)
#include <cuda_runtime.h>

#define B  16
#define T2 2048
#define T1 512
#define F  128
#define NROWS (B * T2)

// scratch (allocation-free rule: __device__ globals)
__device__ float g_prop[NROWS];
__device__ float g_act [NROWS];
__device__ float g_imv [NROWS];
__device__ float g_zinv[NROWS];
__device__ float g_m   [NROWS];
__device__ int   g_vlen[B];

__device__ __forceinline__ float wred(float v) {
#pragma unroll
    for (int o = 16; o; o >>= 1) v += __shfl_xor_sync(0xffffffffu, v, o);
    return v;
}
__device__ __forceinline__ double wredd(double v) {
#pragma unroll
    for (int o = 16; o; o >>= 1) v += __shfl_xor_sync(0xffffffffu, v, o);
    return v;
}
__device__ __forceinline__ int wredi(int v) {
#pragma unroll
    for (int o = 16; o; o >>= 1) v += __shfl_xor_sync(0xffffffffu, v, o);
    return v;
}

// tf32 round-to-nearest (matches cutlass/cuBLAS f32->tf32 input conversion)
__device__ __forceinline__ float tf32r(float x) {
    float y;
    asm("cvt.rna.tf32.f32 %0, %1;" : "=f"(y) : "f"(x));
    return y;
}

// ---------------------------------------------------------------------------
// Kernel 1: one warp per (b,t) row.
//  - imv_proposal[b,t] = sum_s alpha[b,t,s] * s  (exact double accum -> f32)
//  - activity[b,t]     = sigmoid(10*(0.9 - cos(mel[t-1], mel[t]))) * am
// ---------------------------------------------------------------------------
__global__ void k_prop_act(const float* __restrict__ mels,
                           const float* __restrict__ alpha,
                           const int*   __restrict__ mmask) {
    int warp = (blockIdx.x * blockDim.x + threadIdx.x) >> 5;
    int lane = threadIdx.x & 31;
    if (warp >= NROWS) return;
    int t = warp % T2;

    const float4* a4 = (const float4*)(alpha + (size_t)warp * T1);
    double acc = 0.0;
#pragma unroll
    for (int i = 0; i < 4; i++) {
        int idx = lane + i * 32;          // 0..127 float4 per row
        float4 v = a4[idx];
        double s = (double)(idx * 4);
        acc = fma((double)v.x, s, acc);
        acc = fma((double)v.y, s + 1.0, acc);
        acc = fma((double)v.z, s + 2.0, acc);
        acc = fma((double)v.w, s + 3.0, acc);
    }
    acc = wredd(acc);

    float am = (float)mmask[warp];
    float act;
    if (t == 0) {
        act = am;
    } else {
        const float4* m1 = (const float4*)(mels + (size_t)warp * F);
        const float4* m0 = (const float4*)(mels + (size_t)(warp - 1) * F);
        float4 x = m1[lane], y = m0[lane];   // F=128 -> exactly 1 float4/lane
        float dot = x.x * y.x + x.y * y.y + x.z * y.z + x.w * y.w;
        float n1  = x.x * x.x + x.y * x.y + x.z * x.z + x.w * x.w;
        float n0  = y.x * y.x + y.y * y.y + y.z * y.z + y.w * y.w;
        dot = wred(dot); n1 = wred(n1); n0 = wred(n0);
        float c = dot / (fmaxf(sqrtf(n0), 1e-12f) * fmaxf(sqrtf(n1), 1e-12f));
        float z = 10.f * (0.9f - c);
        act = am / (1.f + expf(-z));
    }
    if (lane == 0) { g_prop[warp] = (float)acc; g_act[warp] = act; }
}

// ---------------------------------------------------------------------------
// Kernel 2: one block per batch. eff_delta computed in f32 (mimics ref op
// sequence), prefix scan carried in double (exact) then rounded to f32.
// ---------------------------------------------------------------------------
__global__ void k_scan(const int* __restrict__ mmask,
                       const int* __restrict__ tmask,
                       float* __restrict__ imv_out) {
    int b    = blockIdx.x;
    int tid  = threadIdx.x;       // 256
    int lane = tid & 31, wid = tid >> 5;
    const float* prop = g_prop + b * T2;
    const float* act  = g_act  + b * T2;
    const int*   mm   = mmask  + b * T2;

    __shared__ float  s_imv[T2];
    __shared__ double wsum[8];
    __shared__ int    s_msum, s_tsum;
    __shared__ float  s_scale;
    if (tid == 0) { s_msum = 0; s_tsum = 0; }
    __syncthreads();

    double vals[8];
    double run = 0.0;
    int    msum = 0;
#pragma unroll
    for (int j = 0; j < 8; j++) {
        int t = tid * 8 + j;
        float e = 0.f;
        if (t > 0) {
            e = (prop[t] - prop[t - 1]) * act[t];   // f32, as in reference
            e = fminf(fmaxf(e, 0.f), 1.f);
        }
        run += (double)e;
        vals[j] = run;
        msum += mm[t];
    }
    // warp inclusive scan of per-thread totals (double)
    double tot = run;
#pragma unroll
    for (int o = 1; o < 32; o <<= 1) {
        double n = __shfl_up_sync(0xffffffffu, tot, o);
        if (lane >= o) tot += n;
    }
    if (lane == 31) wsum[wid] = tot;

    // mask sums
    msum = wredi(msum);
    if (lane == 0) atomicAdd(&s_msum, msum);
    int tsum = tmask[b * T1 + tid] + tmask[b * T1 + 256 + tid];
    tsum = wredi(tsum);
    if (lane == 0) atomicAdd(&s_tsum, tsum);
    __syncthreads();

    if (wid == 0 && lane < 8) {
        double w = wsum[lane];
#pragma unroll
        for (int o = 1; o < 8; o <<= 1) {
            double n = __shfl_up_sync(0x000000ffu, w, o);
            if (lane >= o) w += n;
        }
        wsum[lane] = w;
    }
    __syncthreads();

    double base = (wid > 0 ? wsum[wid - 1] : 0.0) + (tot - run);
#pragma unroll
    for (int j = 0; j < 8; j++) s_imv[tid * 8 + j] = (float)(base + vals[j]);
    __syncthreads();

    if (tid == 0) {
        int vlen = s_msum;
        g_vlen[b] = vlen;
        int li = vlen - 1; if (li < 0) li = 0;
        float lastv = fmaxf(s_imv[li] * (float)mm[li], 1e-6f);
        float tl = (float)s_tsum;
        s_scale = fmaxf(tl - 1.f, 0.f) / lastv;   // f32 divide, as in reference
    }
    __syncthreads();

    float sc = s_scale;
#pragma unroll
    for (int j = 0; j < 8; j++) {
        int t = tid * 8 + j;
        float v = s_imv[t] * sc * (float)mm[t];   // f32 mul chain, as in ref
        g_imv[b * T2 + t] = v;
        imv_out[b * T2 + t] = v;
    }
}

// ---------------------------------------------------------------------------
// Kernel 3: per (b,t) softmax normalization over a +/-4 phoneme window.
// (exact in f32: terms outside the window underflow to 0 even in the ref)
// ---------------------------------------------------------------------------
__global__ void k_z(const int* __restrict__ mmask,
                    const int* __restrict__ tmask) {
    int r = blockIdx.x * blockDim.x + threadIdx.x;
    if (r >= NROWS) return;
    int b = r / T2;
    float x  = g_imv[r];
    float am = (float)mmask[r];
    const int* tm = tmask + b * T1;
    int sc = (int)floorf(x + 0.5f);
    float l[9];
    float m = -1e30f;
#pragma unroll
    for (int k = 0; k < 9; k++) {
        int s = sc + k - 4;
        float lv = -1e30f;
        if (s >= 0 && s < T1 && tm[s]) {
            float d  = x - (float)s;
            float ds = d * d;
            lv = -10.f * ds;
        }
        l[k] = lv;
        m = fmaxf(m, lv);
    }
    float Z = 0.f;
#pragma unroll
    for (int k = 0; k < 9; k++)
        if (l[k] > -1e29f) Z += expf(l[k] - m);
    g_m[r]    = m;
    g_zinv[r] = (Z > 0.f) ? am / Z : 0.f;
}

// ---------------------------------------------------------------------------
// Kernel 4: gather. Block = (8 phonemes, 1 batch), 128 threads = F lanes.
// Two phases: (A) durations (f32, matches ref reduce), (B) normalized
// weights + mels rounded to TF32, f32 accumulation — emulating the
// reference's cuBLAS TF32 einsum('bst,btf->bsf').
// ---------------------------------------------------------------------------
__global__ void __launch_bounds__(128) k_gather(
        const float* __restrict__ mels,
        const int*   __restrict__ tmask,
        float* __restrict__ aligned,
        float* __restrict__ durs) {
    int b   = blockIdx.y;
    int s0  = blockIdx.x * 8;
    int tid = threadIdx.x;
    const float* imv = g_imv + b * T2;
    int vlen = g_vlen[b];

    // binary search for t-range where any of s0..s0+7 can get nonzero gamma
    float lob = (float)s0 - 4.6f;
    float hib = (float)(s0 + 7) + 4.6f;
    int lo = 0, hi = vlen;
    while (lo < hi) { int mid = (lo + hi) >> 1; if (imv[mid] < lob) lo = mid + 1; else hi = mid; }
    int t_lo = lo;
    lo = t_lo; hi = vlen;
    while (lo < hi) { int mid = (lo + hi) >> 1; if (imv[mid] <= hib) lo = mid + 1; else hi = mid; }
    int t_hi = lo;

    __shared__ float s_g[8][132];
    __shared__ float s_tm[8];
    __shared__ float s_w[4][8];
    __shared__ float s_dur[8];
    if (tid < 8) s_tm[tid] = (float)tmask[b * T1 + s0 + tid];
    __syncthreads();

    float durp[8];
#pragma unroll
    for (int k = 0; k < 8; k++) durp[k] = 0.f;

    // ---- Phase A: durations (unnormalized gamma mass per phoneme) ----
    for (int t = t_lo + tid; t < t_hi; t += 128) {
        float x  = imv[t];
        float zi = g_zinv[b * T2 + t];
        float mm = g_m[b * T2 + t];
#pragma unroll
        for (int k = 0; k < 8; k++) {
            float d  = x - (float)(s0 + k);
            float ds = d * d;
            float arg = fminf(-10.f * ds - mm, 80.f);
            durp[k] += expf(arg) * zi * s_tm[k];
        }
    }
#pragma unroll
    for (int k = 0; k < 8; k++) durp[k] = wred(durp[k]);
    int lane = tid & 31, wid = tid >> 5;
    if (lane == 0) {
#pragma unroll
        for (int k = 0; k < 8; k++) s_w[wid][k] = durp[k];
    }
    __syncthreads();
    if (tid < 8) {
        float d = s_w[0][tid] + s_w[1][tid] + s_w[2][tid] + s_w[3][tid];
        s_dur[tid] = d;
        durs[b * T1 + s0 + tid] = d * s_tm[tid];
    }
    __syncthreads();

    float invd[8];
#pragma unroll
    for (int k = 0; k < 8; k++) invd[k] = s_dur[k] + 1e-8f;

    // ---- Phase B: TF32-emulated attention pooling ----
    float acc[8];
#pragma unroll
    for (int k = 0; k < 8; k++) acc[k] = 0.f;

    for (int t0 = t_lo; t0 < t_hi; t0 += 128) {
        int t = t0 + tid;
        if (t < t_hi) {
            float x  = imv[t];
            float zi = g_zinv[b * T2 + t];
            float mm = g_m[b * T2 + t];
#pragma unroll
            for (int k = 0; k < 8; k++) {
                float d  = x - (float)(s0 + k);
                float ds = d * d;
                float arg = fminf(-10.f * ds - mm, 80.f);
                float g   = expf(arg) * zi * s_tm[k];
                s_g[k][tid] = tf32r(g / invd[k]);   // normalized weight -> tf32
            }
        } else {
#pragma unroll
            for (int k = 0; k < 8; k++) s_g[k][tid] = 0.f;
        }
        __syncthreads();

        int nt = t_hi - t0; if (nt > 128) nt = 128;
        const float* mp = mels + ((size_t)(b * T2 + t0)) * F + tid;
        for (int tt = 0; tt < nt; tt++) {
            float mv = tf32r(mp[(size_t)tt * F]);   // mel operand -> tf32
#pragma unroll
            for (int k = 0; k < 8; k++) acc[k] = fmaf(s_g[k][tt], mv, acc[k]);
        }
        __syncthreads();
    }

#pragma unroll
    for (int k = 0; k < 8; k++) {
        aligned[((size_t)(b * T1 + s0 + k)) * F + tid] = acc[k] * s_tm[k];
    }
}

// ---------------------------------------------------------------------------
extern "C" void kernel_launch(void* const* d_in, const int* in_sizes, int n_in,
                              void* d_out, int out_size) {
    const float* mels  = (const float*)d_in[0];
    const float* alpha = (const float*)d_in[1];
    const int*   mmask = (const int*)d_in[2];
    const int*   tmask = (const int*)d_in[3];

    float* out_al  = (float*)d_out;                       // [B,T1,F]
    float* out_dur = out_al + (size_t)B * T1 * F;         // [B,T1]
    float* out_imv = out_dur + (size_t)B * T1;            // [B,T2]

    (void)in_sizes; (void)n_in; (void)out_size;

    // 1) proposal + activity : 1 warp per (b,t)
    {
        int warps = NROWS;
        int threads = 256;
        int blocks = (warps * 32 + threads - 1) / threads;
        k_prop_act<<<blocks, threads>>>(mels, alpha, mmask);
    }
    // 2) scan + rescale : 1 block per batch
    k_scan<<<B, 256>>>(mmask, tmask, out_imv);
    // 3) softmax normalizers
    k_z<<<NROWS / 256, 256>>>(mmask, tmask);
    // 4) gather: aligned_mels + durations
    {
        dim3 grid(T1 / 8, B);
        k_gather<<<grid, 128>>>(mels, tmask, out_al, out_dur);
    }
}

// round 9
// speedup vs baseline: 2.7275x; 2.7275x over previous
#include <cuda_runtime.h>

#define B  16
#define T2 2048
#define T1 512
#define F  128
#define NROWS (B * T2)

// scratch (allocation-free rule: __device__ globals)
__device__ float g_prop[NROWS];
__device__ float g_act [NROWS];
__device__ float g_imv [NROWS];
__device__ float g_zinv[NROWS];
__device__ float g_m   [NROWS];
__device__ int   g_vlen[B];

__device__ __forceinline__ float wred(float v) {
#pragma unroll
    for (int o = 16; o; o >>= 1) v += __shfl_xor_sync(0xffffffffu, v, o);
    return v;
}
__device__ __forceinline__ int wredi(int v) {
#pragma unroll
    for (int o = 16; o; o >>= 1) v += __shfl_xor_sync(0xffffffffu, v, o);
    return v;
}

// tf32 round-to-nearest (matches cuBLAS f32->tf32 input conversion)
__device__ __forceinline__ float tf32r(float x) {
    float y;
    asm("cvt.rna.tf32.f32 %0, %1;" : "=f"(y) : "f"(x));
    return y;
}

// Neumaier compensated add: (sum, comp) += x
__device__ __forceinline__ void neum_add(float& sum, float& comp, float x) {
    float t = sum + x;
    float corr = (fabsf(sum) >= fabsf(x)) ? ((sum - t) + x) : ((x - t) + sum);
    comp += corr;
    sum = t;
}

// ---------------------------------------------------------------------------
// Kernel 1: one warp per (b,t) row.
//  - imv_proposal[b,t] = sum_s alpha[b,t,s] * s
//    (TwoProd + Neumaier compensated f32 ~= exact double, but on the f32 pipe)
//  - activity[b,t]     = sigmoid(10*(0.9 - cos(mel[t-1], mel[t]))) * am
// ---------------------------------------------------------------------------
__global__ void k_prop_act(const float* __restrict__ mels,
                           const float* __restrict__ alpha,
                           const int*   __restrict__ mmask) {
    int warp = (blockIdx.x * blockDim.x + threadIdx.x) >> 5;
    int lane = threadIdx.x & 31;
    if (warp >= NROWS) return;
    int t = warp % T2;

    const float4* a4 = (const float4*)(alpha + (size_t)warp * T1);
    float sum = 0.f, comp = 0.f;
#pragma unroll
    for (int i = 0; i < 4; i++) {
        int idx = lane + i * 32;          // 0..127 float4 per row
        float4 v = a4[idx];
        float s = (float)(idx * 4);
        // component x
        {
            float p = v.x * s;
            float e = fmaf(v.x, s, -p);   // exact product error
            neum_add(sum, comp, p);
            comp += e;
        }
        {
            float s1 = s + 1.f;
            float p = v.y * s1;
            float e = fmaf(v.y, s1, -p);
            neum_add(sum, comp, p);
            comp += e;
        }
        {
            float s2 = s + 2.f;
            float p = v.z * s2;
            float e = fmaf(v.z, s2, -p);
            neum_add(sum, comp, p);
            comp += e;
        }
        {
            float s3 = s + 3.f;
            float p = v.w * s3;
            float e = fmaf(v.w, s3, -p);
            neum_add(sum, comp, p);
            comp += e;
        }
    }
    // compensated warp reduction of (sum, comp) pairs
#pragma unroll
    for (int o = 16; o; o >>= 1) {
        float oh = __shfl_xor_sync(0xffffffffu, sum,  o);
        float ol = __shfl_xor_sync(0xffffffffu, comp, o);
        float tt = sum + oh;
        float corr = (fabsf(sum) >= fabsf(oh)) ? ((sum - tt) + oh) : ((oh - tt) + sum);
        sum = tt;
        comp = comp + ol + corr;
    }
    float prop = sum + comp;

    float am = (float)mmask[warp];
    float act;
    if (t == 0) {
        act = am;
    } else {
        const float4* m1 = (const float4*)(mels + (size_t)warp * F);
        const float4* m0 = (const float4*)(mels + (size_t)(warp - 1) * F);
        float4 x = m1[lane], y = m0[lane];   // F=128 -> exactly 1 float4/lane
        float dot = x.x * y.x + x.y * y.y + x.z * y.z + x.w * y.w;
        float n1  = x.x * x.x + x.y * x.y + x.z * x.z + x.w * x.w;
        float n0  = y.x * y.x + y.y * y.y + y.z * y.z + y.w * y.w;
        dot = wred(dot); n1 = wred(n1); n0 = wred(n0);
        float c = dot / (fmaxf(sqrtf(n0), 1e-12f) * fmaxf(sqrtf(n1), 1e-12f));
        float z = 10.f * (0.9f - c);
        act = am / (1.f + __expf(-z));
    }
    if (lane == 0) { g_prop[warp] = prop; g_act[warp] = act; }
}

// ---------------------------------------------------------------------------
// Kernel 2 (fused scan + rescale + softmax normalizers):
// one block per batch. eff_delta in f32 (ref op order), prefix scan carried
// in double (tiny kernel, exact), rescale, then per-frame window max m and
// am/Z computed in-place from shared imv.
// ---------------------------------------------------------------------------
__global__ void k_scan(const int* __restrict__ mmask,
                       const int* __restrict__ tmask,
                       float* __restrict__ imv_out) {
    int b    = blockIdx.x;
    int tid  = threadIdx.x;       // 256
    int lane = tid & 31, wid = tid >> 5;
    const float* prop = g_prop + b * T2;
    const float* act  = g_act  + b * T2;
    const int*   mm   = mmask  + b * T2;

    __shared__ float  s_imv[T2];
    __shared__ float  s_tmf[T1];
    __shared__ double wsum[8];
    __shared__ int    s_msum, s_tsum;
    __shared__ float  s_scale;
    if (tid == 0) { s_msum = 0; s_tsum = 0; }
    // stage text mask as float
    s_tmf[tid]       = (float)tmask[b * T1 + tid];
    s_tmf[tid + 256] = (float)tmask[b * T1 + 256 + tid];
    __syncthreads();

    double vals[8];
    double run = 0.0;
    int    msum = 0;
#pragma unroll
    for (int j = 0; j < 8; j++) {
        int t = tid * 8 + j;
        float e = 0.f;
        if (t > 0) {
            e = (prop[t] - prop[t - 1]) * act[t];   // f32, as in reference
            e = fminf(fmaxf(e, 0.f), 1.f);
        }
        run += (double)e;
        vals[j] = run;
        msum += mm[t];
    }
    // warp inclusive scan of per-thread totals (double)
    double tot = run;
#pragma unroll
    for (int o = 1; o < 32; o <<= 1) {
        double n = __shfl_up_sync(0xffffffffu, tot, o);
        if (lane >= o) tot += n;
    }
    if (lane == 31) wsum[wid] = tot;

    // mask sums
    msum = wredi(msum);
    if (lane == 0) atomicAdd(&s_msum, msum);
    int tsum = tmask[b * T1 + tid] + tmask[b * T1 + 256 + tid];
    tsum = wredi(tsum);
    if (lane == 0) atomicAdd(&s_tsum, tsum);
    __syncthreads();

    if (wid == 0 && lane < 8) {
        double w = wsum[lane];
#pragma unroll
        for (int o = 1; o < 8; o <<= 1) {
            double n = __shfl_up_sync(0x000000ffu, w, o);
            if (lane >= o) w += n;
        }
        wsum[lane] = w;
    }
    __syncthreads();

    double base = (wid > 0 ? wsum[wid - 1] : 0.0) + (tot - run);
#pragma unroll
    for (int j = 0; j < 8; j++) s_imv[tid * 8 + j] = (float)(base + vals[j]);
    __syncthreads();

    if (tid == 0) {
        int vlen = s_msum;
        g_vlen[b] = vlen;
        int li = vlen - 1; if (li < 0) li = 0;
        float lastv = fmaxf(s_imv[li] * (float)mm[li], 1e-6f);
        float tl = (float)s_tsum;
        s_scale = fmaxf(tl - 1.f, 0.f) / lastv;   // f32 divide, as in reference
    }
    __syncthreads();

    float sc = s_scale;
#pragma unroll
    for (int j = 0; j < 8; j++) {
        int t = tid * 8 + j;
        float am = (float)mm[t];
        float v = s_imv[t] * sc * am;   // f32 mul chain, as in ref
        g_imv[b * T2 + t]   = v;
        imv_out[b * T2 + t] = v;

        // fused softmax normalizer over +/-4 phoneme window
        int ci = (int)floorf(v + 0.5f);
        float m = -1e30f;
#pragma unroll
        for (int k = 0; k < 9; k++) {
            int s = ci + k - 4;
            if (s >= 0 && s < T1 && s_tmf[s] != 0.f) {
                float d = v - (float)s;
                m = fmaxf(m, -10.f * d * d);
            }
        }
        float Z = 0.f;
#pragma unroll
        for (int k = 0; k < 9; k++) {
            int s = ci + k - 4;
            if (s >= 0 && s < T1 && s_tmf[s] != 0.f) {
                float d = v - (float)s;
                Z += __expf(-10.f * d * d - m);
            }
        }
        g_m[b * T2 + t]    = m;
        g_zinv[b * T2 + t] = (Z > 0.f) ? am / Z : 0.f;
    }
}

// ---------------------------------------------------------------------------
// Kernel 3: gather. Block = (8 phonemes, 1 batch), 128 threads = F lanes.
// Phase A: durations (f32). Phase B: normalized weights + mels rounded to
// TF32, f32 accumulation — emulating the reference's cuBLAS TF32 einsum.
// ---------------------------------------------------------------------------
__global__ void __launch_bounds__(128) k_gather(
        const float* __restrict__ mels,
        const int*   __restrict__ tmask,
        float* __restrict__ aligned,
        float* __restrict__ durs) {
    int b   = blockIdx.y;
    int s0  = blockIdx.x * 8;
    int tid = threadIdx.x;
    const float* imv = g_imv + b * T2;
    int vlen = g_vlen[b];

    // binary search for t-range where any of s0..s0+7 can get nonzero gamma
    float lob = (float)s0 - 4.6f;
    float hib = (float)(s0 + 7) + 4.6f;
    int lo = 0, hi = vlen;
    while (lo < hi) { int mid = (lo + hi) >> 1; if (imv[mid] < lob) lo = mid + 1; else hi = mid; }
    int t_lo = lo;
    lo = t_lo; hi = vlen;
    while (lo < hi) { int mid = (lo + hi) >> 1; if (imv[mid] <= hib) lo = mid + 1; else hi = mid; }
    int t_hi = lo;

    __shared__ float s_g[8][132];
    __shared__ float s_tm[8];
    __shared__ float s_w[4][8];
    __shared__ float s_dur[8];
    if (tid < 8) s_tm[tid] = (float)tmask[b * T1 + s0 + tid];
    __syncthreads();

    float durp[8];
#pragma unroll
    for (int k = 0; k < 8; k++) durp[k] = 0.f;

    // ---- Phase A: durations (unnormalized gamma mass per phoneme) ----
    for (int t = t_lo + tid; t < t_hi; t += 128) {
        float x  = imv[t];
        float zi = g_zinv[b * T2 + t];
        float mm = g_m[b * T2 + t];
#pragma unroll
        for (int k = 0; k < 8; k++) {
            float d  = x - (float)(s0 + k);
            float arg = fminf(-10.f * d * d - mm, 80.f);
            durp[k] += __expf(arg) * zi * s_tm[k];
        }
    }
#pragma unroll
    for (int k = 0; k < 8; k++) durp[k] = wred(durp[k]);
    int lane = tid & 31, wid = tid >> 5;
    if (lane == 0) {
#pragma unroll
        for (int k = 0; k < 8; k++) s_w[wid][k] = durp[k];
    }
    __syncthreads();
    if (tid < 8) {
        float d = s_w[0][tid] + s_w[1][tid] + s_w[2][tid] + s_w[3][tid];
        s_dur[tid] = d;
        durs[b * T1 + s0 + tid] = d * s_tm[tid];
    }
    __syncthreads();

    float invd[8];
#pragma unroll
    for (int k = 0; k < 8; k++) invd[k] = s_dur[k] + 1e-8f;

    // ---- Phase B: TF32-emulated attention pooling ----
    float acc[8];
#pragma unroll
    for (int k = 0; k < 8; k++) acc[k] = 0.f;

    for (int t0 = t_lo; t0 < t_hi; t0 += 128) {
        int t = t0 + tid;
        if (t < t_hi) {
            float x  = imv[t];
            float zi = g_zinv[b * T2 + t];
            float mm = g_m[b * T2 + t];
#pragma unroll
            for (int k = 0; k < 8; k++) {
                float d  = x - (float)(s0 + k);
                float arg = fminf(-10.f * d * d - mm, 80.f);
                float g   = __expf(arg) * zi * s_tm[k];
                s_g[k][tid] = tf32r(g / invd[k]);   // normalized weight -> tf32
            }
        } else {
#pragma unroll
            for (int k = 0; k < 8; k++) s_g[k][tid] = 0.f;
        }
        __syncthreads();

        int nt = t_hi - t0; if (nt > 128) nt = 128;
        const float* mp = mels + ((size_t)(b * T2 + t0)) * F + tid;
        for (int tt = 0; tt < nt; tt++) {
            float mv = tf32r(mp[(size_t)tt * F]);   // mel operand -> tf32
#pragma unroll
            for (int k = 0; k < 8; k++) acc[k] = fmaf(s_g[k][tt], mv, acc[k]);
        }
        __syncthreads();
    }

#pragma unroll
    for (int k = 0; k < 8; k++) {
        aligned[((size_t)(b * T1 + s0 + k)) * F + tid] = acc[k] * s_tm[k];
    }
}

// ---------------------------------------------------------------------------
extern "C" void kernel_launch(void* const* d_in, const int* in_sizes, int n_in,
                              void* d_out, int out_size) {
    const float* mels  = (const float*)d_in[0];
    const float* alpha = (const float*)d_in[1];
    const int*   mmask = (const int*)d_in[2];
    const int*   tmask = (const int*)d_in[3];

    float* out_al  = (float*)d_out;                       // [B,T1,F]
    float* out_dur = out_al + (size_t)B * T1 * F;         // [B,T1]
    float* out_imv = out_dur + (size_t)B * T1;            // [B,T2]

    (void)in_sizes; (void)n_in; (void)out_size;

    // 1) proposal + activity : 1 warp per (b,t)
    {
        int warps = NROWS;
        int threads = 256;
        int blocks = (warps * 32 + threads - 1) / threads;
        k_prop_act<<<blocks, threads>>>(mels, alpha, mmask);
    }
    // 2) scan + rescale + softmax normalizers : 1 block per batch
    k_scan<<<B, 256>>>(mmask, tmask, out_imv);
    // 3) gather: aligned_mels + durations
    {
        dim3 grid(T1 / 8, B);
        k_gather<<<grid, 128>>>(mels, tmask, out_al, out_dur);
    }
}